// round 11
// baseline (speedup 1.0000x reference)
#include <cuda_runtime.h>
#include <cuda_fp16.h>
#include <cstdint>

// SGNS loss, fp16-everything scheme, conversion-optimized:
//  K1 (fused): convert BOTH tables fp32->fp16 in one launch.
//     - 16 elems/thread: 4 independent LDG.128 (MLP=4) + 2 STG.128
//     - loads evict_first (streamed once), stores evict_last (pin 51MB
//       scratch in L2 -> no write-back, main pass reads hit L2)
//  K2: SGNS main pass (R10 champion): uint4-per-lane fp16 gathers,
//      distributed index fetch, parallel log-sigmoid epilogue, __stwt out.
// Main pass is at the LTS service-rate floor (~470MB / ~31us); remaining
// time is the conversion pre-pass (was 25us, floor ~14us).

#define D 128
#define KNEG 5
#define LPP 8          // lanes per pair
#define VMAX 100000

// fp16 mirrors: V*D halves = 25.6MB each
__device__ uint4 g_w_h[(size_t)VMAX * D / 8];
__device__ uint4 g_e_h[(size_t)VMAX * D / 8];

__device__ __forceinline__ float log_sigmoid(float x) {
    return fminf(x, 0.0f) - log1pf(__expf(-fabsf(x)));
}

__device__ __forceinline__ float4 ldg_f4_hint(const void* p, uint64_t pol) {
    float4 v;
    asm volatile("ld.global.nc.L2::cache_hint.v4.f32 {%0,%1,%2,%3}, [%4], %5;"
                 : "=f"(v.x), "=f"(v.y), "=f"(v.z), "=f"(v.w)
                 : "l"(p), "l"(pol));
    return v;
}

__device__ __forceinline__ uint4 ldg_u4_hint(const void* p, uint64_t pol) {
    uint4 v;
    asm volatile("ld.global.nc.L2::cache_hint.v4.b32 {%0,%1,%2,%3}, [%4], %5;"
                 : "=r"(v.x), "=r"(v.y), "=r"(v.z), "=r"(v.w)
                 : "l"(p), "l"(pol));
    return v;
}

__device__ __forceinline__ void stg_u4_hint(void* p, uint4 v, uint64_t pol) {
    asm volatile("st.global.L2::cache_hint.v4.b32 [%0], {%1,%2,%3,%4}, %5;"
                 :: "l"(p), "r"(v.x), "r"(v.y), "r"(v.z), "r"(v.w), "l"(pol)
                 : "memory");
}

__device__ __forceinline__ uint4 pack8(float4 a, float4 b) {
    uint4 o;
    __half2 h;
    h = __floats2half2_rn(a.x, a.y); o.x = *reinterpret_cast<const uint32_t*>(&h);
    h = __floats2half2_rn(a.z, a.w); o.y = *reinterpret_cast<const uint32_t*>(&h);
    h = __floats2half2_rn(b.x, b.y); o.z = *reinterpret_cast<const uint32_t*>(&h);
    h = __floats2half2_rn(b.z, b.w); o.w = *reinterpret_cast<const uint32_t*>(&h);
    return o;
}

// K1: fused fp32 -> fp16 conversion of both tables, 16 elements per thread
__global__ void __launch_bounds__(256) convert_both_kernel(
    const float* __restrict__ e_src, const float* __restrict__ w_src,
    int n_each)
{
    uint64_t pol_first, pol_last;
    asm("createpolicy.fractional.L2::evict_first.b64 %0, 1.0;" : "=l"(pol_first));
    asm("createpolicy.fractional.L2::evict_last.b64 %0, 1.0;"  : "=l"(pol_last));

    int i = (blockIdx.x * blockDim.x + threadIdx.x) * 16;
    const float* src;
    uint4* dst;
    if (i < n_each) {
        src = e_src; dst = g_e_h;
    } else {
        src = w_src; dst = g_w_h; i -= n_each;
    }
    if (i >= n_each) return;

    // 4 independent 16B loads (MLP=4)
    float4 a0 = ldg_f4_hint(src + i,      pol_first);
    float4 a1 = ldg_f4_hint(src + i + 4,  pol_first);
    float4 a2 = ldg_f4_hint(src + i + 8,  pol_first);
    float4 a3 = ldg_f4_hint(src + i + 12, pol_first);

    stg_u4_hint(dst + (i >> 3),     pack8(a0, a1), pol_last);
    stg_u4_hint(dst + (i >> 3) + 1, pack8(a2, a3), pol_last);
}

// K2: main SGNS pass (all-fp16 gathers, fp32 accumulate)
__global__ void __launch_bounds__(256) sgns_loss_kernel(
    const int* __restrict__ tgt_ids,
    const int* __restrict__ ctx_ids,
    const int* __restrict__ neg_ids,
    float*     __restrict__ out,
    int N)
{
    const int tid  = blockIdx.x * blockDim.x + threadIdx.x;
    const int pair = tid >> 3;
    const int lane = threadIdx.x & (LPP - 1);
    if (pair >= N) return;

    uint64_t pol_last;
    asm("createpolicy.fractional.L2::evict_last.b64 %0, 1.0;" : "=l"(pol_last));

    const unsigned gmask = 0xFFu << ((threadIdx.x & 31) & ~(LPP - 1));

    // Distributed index fetch: slot 0=tgt, 1=ctx, 2..6=neg[0..4]
    int myidx = 0;
    if (lane == 0)      myidx = __ldg(tgt_ids + pair);
    else if (lane == 1) myidx = __ldg(ctx_ids + pair);
    else if (lane < 7)  myidx = __ldg(neg_ids + pair * KNEG + (lane - 2));

    // fp16 rows are 256B
    const unsigned t_off = (unsigned)__shfl_sync(gmask, myidx, 0, LPP) << 8;
    unsigned roff[1 + KNEG];
#pragma unroll
    for (int j = 0; j < 1 + KNEG; j++)
        roff[j] = (unsigned)__shfl_sync(gmask, myidx, 1 + j, LPP) << 8;

    const char* e_b = reinterpret_cast<const char*>(g_e_h);
    const char* w_b = reinterpret_cast<const char*>(g_w_h);
    const unsigned lane16 = (unsigned)lane * 16u;  // uint4 slot in the 128B line

    // input row: chunk i (i=0,1) = uint4 at byte 16l + 128i -> dims 8l+64i..+7
    float ivf[16];
#pragma unroll
    for (int i = 0; i < 2; i++) {
        uint4 u = ldg_u4_hint(e_b + t_off + lane16 + 128u * i, pol_last);
        const __half2* h = reinterpret_cast<const __half2*>(&u);
#pragma unroll
        for (int q = 0; q < 4; q++) {
            float2 f = __half22float2(h[q]);
            ivf[i * 8 + q * 2 + 0] = f.x;
            ivf[i * 8 + q * 2 + 1] = f.y;
        }
    }

    // double-buffered walk over the 6 fp16 w rows
    uint4 cur[2], nxt[2];
#pragma unroll
    for (int i = 0; i < 2; i++)
        cur[i] = ldg_u4_hint(w_b + roff[0] + lane16 + 128u * i, pol_last);

    float s[1 + KNEG];
#pragma unroll
    for (int j = 0; j < 1 + KNEG; j++) {
        if (j < KNEG) {
#pragma unroll
            for (int i = 0; i < 2; i++)
                nxt[i] = ldg_u4_hint(w_b + roff[j + 1] + lane16 + 128u * i, pol_last);
        }
        float acc = 0.f;
#pragma unroll
        for (int i = 0; i < 2; i++) {
            const __half2* h = reinterpret_cast<const __half2*>(&cur[i]);
#pragma unroll
            for (int q = 0; q < 4; q++) {
                float2 f = __half22float2(h[q]);
                acc = fmaf(ivf[i * 8 + q * 2 + 0], f.x, acc);
                acc = fmaf(ivf[i * 8 + q * 2 + 1], f.y, acc);
            }
        }
        s[j] = acc;
        if (j < KNEG) {
            cur[0] = nxt[0];
            cur[1] = nxt[1];
        }
    }

    // 3-stage butterfly: all lanes end with all 6 sums
#pragma unroll
    for (int j = 0; j < 1 + KNEG; j++) {
#pragma unroll
        for (int off = LPP / 2; off > 0; off >>= 1)
            s[j] += __shfl_xor_sync(gmask, s[j], off, LPP);
    }

    // Parallel epilogue: lanes 0..5 each evaluate one log-sigmoid term
    float x = (lane == 0) ? s[0] : -s[lane < 6 ? lane : 0];
    float term = log_sigmoid(x);
    if (lane >= 6) term = 0.f;
#pragma unroll
    for (int off = LPP / 2; off > 0; off >>= 1)
        term += __shfl_xor_sync(gmask, term, off, LPP);

    if (lane == 0)
        __stwt(out + pair, -term);
}

extern "C" void kernel_launch(void* const* d_in, const int* in_sizes, int n_in,
                              void* d_out, int out_size) {
    const float* emb     = (const float*)d_in[0];
    const float* out_w   = (const float*)d_in[1];
    const int*   tgt_ids = (const int*)d_in[2];
    const int*   ctx_ids = (const int*)d_in[3];
    const int*   neg_ids = (const int*)d_in[4];
    float*       out     = (float*)d_out;

    const int n_each = in_sizes[0];           // V * D elements per table
    const int N      = in_sizes[2];           // number of pairs

    // K1: fused conversion of both tables (16 elems/thread)
    {
        const int threads = 256;
        const long total_threads = 2L * n_each / 16;
        const int blocks = (int)((total_threads + threads - 1) / threads);
        convert_both_kernel<<<blocks, threads>>>(emb, out_w, n_each);
    }

    // K2: main pass
    {
        const int threads = 256;               // 32 pairs per block
        const int pairs_per_block = threads / LPP;
        const int blocks = (N + pairs_per_block - 1) / pairs_per_block;
        sgns_loss_kernel<<<blocks, threads>>>(tgt_ids, ctx_ids, neg_ids, out, N);
    }
}